// round 1
// baseline (speedup 1.0000x reference)
#include <cuda_runtime.h>

#define FULLMASK 0xFFFFFFFFu

struct KParams {
    const float *x, *ap1, *ap2, *am1, *am2, *g0;
    const float *w[11];
    const float *b[11];
    const float *root_w, *root_b;
    float *out;
};

__device__ __forceinline__ float4 ld4(const float* p) { return *reinterpret_cast<const float4*>(p); }
__device__ __forceinline__ float2 ld2(const float* p) { return *reinterpret_cast<const float2*>(p); }

#define LD12(dst, base) do { \
    float4 _a = ld4(base); float4 _b = ld4((base) + 4); float4 _c = ld4((base) + 8); \
    dst[0]=_a.x; dst[1]=_a.y; dst[2]=_a.z; dst[3]=_a.w; \
    dst[4]=_b.x; dst[5]=_b.y; dst[6]=_b.z; dst[7]=_b.w; \
    dst[8]=_c.x; dst[9]=_c.y; dst[10]=_c.z; dst[11]=_c.w; } while(0)

__device__ __forceinline__ float leaky(float y) {
    // y>=0 ? y : 0.01*y, branchless on fma/alu pipes
    return fmaf(0.01f, fminf(y, 0.f), fmaxf(y, 0.f));
}

__device__ __forceinline__ float synapse(float xv, float a1, float a2,
                                          float m1, float m2, float gz) {
    float u = fminf(fmaxf(fmaf(a1, xv, a2), -60.f), 60.f);
    float v = fminf(fmaxf(fmaf(m1, xv, m2), -60.f), 60.f);
    float gp = __expf(u);
    float gm = __expf(v);
    float num = fmaf(gp, 50.f, fmaf(gm, -70.f, gz * (-65.f)));
    float den = (gp + gm) + gz;
    return __fdividef(num, den);
}

__global__ void __launch_bounds__(256, 2) ktree_kernel(KParams P)
{
    const int lane = threadIdx.x & 31;
    const int warp = threadIdx.x >> 5;
    const int row  = (blockIdx.x << 3) + warp;
    if (row >= 8192) return;

    const float* xr = P.x + (size_t)row * 3072 + lane * 96;

    // K=256-level node values for each r (8 per lane)
    float n256[2][8];

#pragma unroll
    for (int j = 0; j < 8; ++j) {
        // x: 12 leaves, streaming loads (no cross-warp reuse)
        float4 xa = __ldcs((const float4*)(xr + 12 * j));
        float4 xb = __ldcs((const float4*)(xr + 12 * j + 4));
        float4 xc = __ldcs((const float4*)(xr + 12 * j + 8));
        float xs[12] = {xa.x, xa.y, xa.z, xa.w, xb.x, xb.y, xb.z, xb.w,
                        xc.x, xc.y, xc.z, xc.w};

#pragma unroll
        for (int r = 0; r < 2; ++r) {
            const int off = lane * 96 + 12 * j;      // leaf offset within (r)-slice
            const int pb  = r * 3072 + off;

            float a1[12], a2[12], m1[12], m2[12], gg[12];
            LD12(a1, P.ap1 + pb);
            LD12(a2, P.ap2 + pb);
            LD12(m1, P.am1 + pb);
            LD12(m2, P.am2 + pb);
            LD12(gg, P.g0  + pb);

            float s[12];
#pragma unroll
            for (int t = 0; t < 12; ++t)
                s[t] = synapse(xs[t], a1[t], a2[t], m1[t], m2[t], gg[t]);

            // level 0: f=3, nodes (32*lane + 4j + t), t=0..3
            // w0 layout (R,1024,3): r*3072 + node*3 ; node*3 = 96*lane + 12*j = off
            float w0v[12];
            LD12(w0v, P.w[0] + r * 3072 + off);
            float4 b0v = ld4(P.b[0] + r * 1024 + lane * 32 + 4 * j);
            float n1_0 = leaky(fmaf(s[2],  w0v[2],  fmaf(s[1],  w0v[1],  fmaf(s[0], w0v[0],  b0v.x))));
            float n1_1 = leaky(fmaf(s[5],  w0v[5],  fmaf(s[4],  w0v[4],  fmaf(s[3], w0v[3],  b0v.y))));
            float n1_2 = leaky(fmaf(s[8],  w0v[8],  fmaf(s[7],  w0v[7],  fmaf(s[6], w0v[6],  b0v.z))));
            float n1_3 = leaky(fmaf(s[11], w0v[11], fmaf(s[10], w0v[10], fmaf(s[9], w0v[9],  b0v.w))));

            // level 1: f=2, nodes (16*lane + 2j + t); w1 (R,512,2): idx r*1024 + node*2
            float4 w1v = ld4(P.w[1] + r * 1024 + lane * 32 + 4 * j);
            float2 b1v = ld2(P.b[1] + r * 512 + lane * 16 + 2 * j);
            float n2_0 = leaky(fmaf(n1_1, w1v.y, fmaf(n1_0, w1v.x, b1v.x)));
            float n2_1 = leaky(fmaf(n1_3, w1v.w, fmaf(n1_2, w1v.z, b1v.y)));

            // level 2: node (8*lane + j); w2 (R,256,2): idx r*512 + node*2
            float2 w2v = ld2(P.w[2] + r * 512 + lane * 16 + 2 * j);
            float  b2v = P.b[2][r * 256 + lane * 8 + j];
            n256[r][j] = leaky(fmaf(n2_1, w2v.y, fmaf(n2_0, w2v.x, b2v)));
        }
    }

    float yfin[2];
#pragma unroll
    for (int r = 0; r < 2; ++r) {
        // level 3: 256->128, nodes (4*lane + t); w3 (R,128,2)
        float w3v[8];
        {
            float4 _a = ld4(P.w[3] + r * 256 + lane * 8);
            float4 _b = ld4(P.w[3] + r * 256 + lane * 8 + 4);
            w3v[0]=_a.x; w3v[1]=_a.y; w3v[2]=_a.z; w3v[3]=_a.w;
            w3v[4]=_b.x; w3v[5]=_b.y; w3v[6]=_b.z; w3v[7]=_b.w;
        }
        float4 b3v = ld4(P.b[3] + r * 128 + lane * 4);
        float m0 = leaky(fmaf(n256[r][1], w3v[1], fmaf(n256[r][0], w3v[0], b3v.x)));
        float m1 = leaky(fmaf(n256[r][3], w3v[3], fmaf(n256[r][2], w3v[2], b3v.y)));
        float m2 = leaky(fmaf(n256[r][5], w3v[5], fmaf(n256[r][4], w3v[4], b3v.z)));
        float m3 = leaky(fmaf(n256[r][7], w3v[7], fmaf(n256[r][6], w3v[6], b3v.w)));

        // level 4: 128->64, nodes (2*lane + t); w4 (R,64,2)
        float4 w4v = ld4(P.w[4] + r * 128 + lane * 4);
        float2 b4v = ld2(P.b[4] + r * 64 + lane * 2);
        float p0 = leaky(fmaf(m1, w4v.y, fmaf(m0, w4v.x, b4v.x)));
        float p1 = leaky(fmaf(m3, w4v.w, fmaf(m2, w4v.z, b4v.y)));

        // level 5: 64->32, node = lane; w5 (R,32,2)
        float2 w5v = ld2(P.w[5] + r * 64 + lane * 2);
        float  b5v = P.b[5][r * 32 + lane];
        float v = leaky(fmaf(p1, w5v.y, fmaf(p0, w5v.x, b5v)));

        // levels 6..10: 32->16->8->4->2->1 via warp shuffles
#pragma unroll
        for (int l = 0; l < 5; ++l) {
            const int S = 16 >> l;
            float lo = __shfl_sync(FULLMASK, v, (2 * lane) & 31);
            float hi = __shfl_sync(FULLMASK, v, (2 * lane + 1) & 31);
            int idx = (lane < S) ? lane : 0;
            const float* wl = P.w[6 + l];
            const float* bl = P.b[6 + l];
            float wlo = wl[r * 2 * S + idx * 2];
            float whi = wl[r * 2 * S + idx * 2 + 1];
            float bb  = bl[r * S + idx];
            v = leaky(fmaf(hi, whi, fmaf(lo, wlo, bb)));
        }
        yfin[r] = v;
    }

    if (lane == 0) {
        float rw0 = P.root_w[0], rw1 = P.root_w[1], rb = P.root_b[0];
        P.out[row] = fmaf(yfin[1], rw1, fmaf(yfin[0], rw0, rb));
    }
}

extern "C" void kernel_launch(void* const* d_in, const int* in_sizes, int n_in,
                              void* d_out, int out_size)
{
    KParams P;
    P.x   = (const float*)d_in[0];
    P.ap1 = (const float*)d_in[1];
    P.ap2 = (const float*)d_in[2];
    P.am1 = (const float*)d_in[3];
    P.am2 = (const float*)d_in[4];
    P.g0  = (const float*)d_in[5];

    // Disambiguate input ordering via sizes:
    // interleaved (dict order):  idx8 = w1 (R*512*2 = 2048)
    // grouped (signature order): idx8 = w2 (R*256*2 = 1024)
    bool interleaved = (in_sizes[8] == 2048);
    for (int i = 0; i < 11; ++i) {
        if (interleaved) {
            P.w[i] = (const float*)d_in[6 + 2 * i];
            P.b[i] = (const float*)d_in[7 + 2 * i];
        } else {
            P.w[i] = (const float*)d_in[6 + i];
            P.b[i] = (const float*)d_in[17 + i];
        }
    }
    P.root_w = (const float*)d_in[28];
    P.root_b = (const float*)d_in[29];
    P.out    = (float*)d_out;

    ktree_kernel<<<1024, 256>>>(P);
}

// round 2
// speedup vs baseline: 3.5638x; 3.5638x over previous
#include <cuda_runtime.h>

// ---------------------------------------------------------------------------
// Problem constants
//   B=8192 rows, R=2, K0=3072 leaves, tree 3072->1024(f=3)->512->...->1 (f=2)
// Decomposition:
//   k1: block = 256 threads (1 thread = 1 row) x 16 K=256-nodes (192 leaves)
//       grid (32 row-tiles, 16 node-tiles). Computes synapse + levels 0..2,
//       writes K=256 node values to scratch in [r][node][row] layout.
//   k2: 1 thread = (row, r). Streams 256 node values (coalesced), collapses
//       levels 3..10 with a fully static unrolled merge network.
//   k3: root combine.
// ---------------------------------------------------------------------------

#define NROWS   8192
#define KSPAN   192      // leaves per node-tile (16 nodes x 12 leaves)
#define CHUNK_K 24       // leaves per x-chunk (2 nodes)
#define XSTRIDE 28       // padded smem row stride (floats): conflict-free LDS.128

__device__ float g_n256[2 * 256 * NROWS];   // [r][node][row]
__device__ float g_y[2 * NROWS];            // [r][row]

struct K1Params {
    const float *x, *ap1, *ap2, *am1, *am2, *g0;
    const float *w0, *b0, *w1, *b1, *w2, *b2;
};
struct K2Params {
    const float* w[8];   // w3..w10
    const float* b[8];   // b3..b10
};

__device__ __forceinline__ float leaky(float y) {
    return fmaf(0.01f, fminf(y, 0.f), fmaxf(y, 0.f));
}

__device__ __forceinline__ float synapse(float xv, float a1, float a2,
                                         float m1, float m2, float gz) {
    float u = fminf(fmaxf(fmaf(a1, xv, a2), -60.f), 60.f);
    float v = fminf(fmaxf(fmaf(m1, xv, m2), -60.f), 60.f);
    float gp = __expf(u);
    float gm = __expf(v);
    float num = fmaf(gp, 50.f, fmaf(gm, -70.f, gz * (-65.f)));
    float den = (gp + gm) + gz;
    return __fdividef(num, den);
}

// 12 floats from shared memory via 3 LDS.128 (base must be 16B aligned)
#define SLD12(dst, ptr) do { \
    float4 _a = *(const float4*)((ptr));     \
    float4 _b = *(const float4*)((ptr) + 4); \
    float4 _c = *(const float4*)((ptr) + 8); \
    dst[0]=_a.x; dst[1]=_a.y; dst[2]=_a.z; dst[3]=_a.w; \
    dst[4]=_b.x; dst[5]=_b.y; dst[6]=_b.z; dst[7]=_b.w; \
    dst[8]=_c.x; dst[9]=_c.y; dst[10]=_c.z; dst[11]=_c.w; } while (0)

__global__ void __launch_bounds__(256) k1_synapse_lower(K1Params P)
{
    // synapse params + w0, per r, for this block's 192-leaf span
    __shared__ float s_syn[6][2][KSPAN];            // a1,a2,m1,m2,g0,w0
    __shared__ float s_b0[2][64];                   // K=1024 nodes in span
    __shared__ float s_w1[2][64];                   // 32 nodes x 2
    __shared__ float s_b1[2][32];
    __shared__ float s_w2[2][32];                   // 16 nodes x 2
    __shared__ float s_b2[2][16];
    __shared__ float s_x[256 * XSTRIDE];            // x chunk, padded rows

    const int tid = threadIdx.x;
    const int r0  = blockIdx.x * 256;               // first row
    const int k0  = blockIdx.y * KSPAN;             // first leaf
    const int row = r0 + tid;

    // ---- stage parameters (coalesced global reads, done once) ----
    {
        const float* srcs[6] = { P.ap1, P.ap2, P.am1, P.am2, P.g0, P.w0 };
#pragma unroll
        for (int a = 0; a < 6; ++a)
            for (int i = tid; i < 2 * KSPAN; i += 256) {
                int r = i / KSPAN, j = i % KSPAN;
                s_syn[a][r][j] = srcs[a][r * 3072 + k0 + j];
            }
        for (int i = tid; i < 128; i += 256) { int r=i>>6, j=i&63; s_b0[r][j] = P.b0[r*1024 + k0/3 + j]; }
        for (int i = tid; i < 128; i += 256) { int r=i>>6, j=i&63; s_w1[r][j] = P.w1[r*1024 + k0/3 + j]; }
        for (int i = tid; i < 64;  i += 256) { int r=i>>5, j=i&31; s_b1[r][j] = P.b1[r*512  + k0/6 + j]; }
        for (int i = tid; i < 64;  i += 256) { int r=i>>5, j=i&31; s_w2[r][j] = P.w2[r*512  + k0/6 + j]; }
        if (tid < 32) { int r=tid>>4, j=tid&15; s_b2[r][j] = P.b2[r*256 + k0/12 + j]; }
    }

    const float* xbase = P.x + (size_t)r0 * 3072 + k0;

#pragma unroll 1
    for (int c = 0; c < KSPAN / CHUNK_K; ++c) {
        __syncthreads();   // previous chunk consumed (also orders param stores)
        // ---- cooperative coalesced load of x chunk: 256 rows x 24 floats ----
#pragma unroll
        for (int it = 0; it < 6; ++it) {
            int i  = it * 256 + tid;          // 0..1535 float4 slots
            int rw = i / 6, cc = i % 6;
            float4 v = __ldcs((const float4*)(xbase + (size_t)rw * 3072 + c * CHUNK_K + cc * 4));
            *(float4*)&s_x[rw * XSTRIDE + cc * 4] = v;
        }
        __syncthreads();

        // ---- this thread's 24 leaves (conflict-free LDS.128) ----
        float xs[CHUNK_K];
#pragma unroll
        for (int q = 0; q < 6; ++q) {
            float4 v = *(const float4*)&s_x[tid * XSTRIDE + q * 4];
            xs[q*4+0]=v.x; xs[q*4+1]=v.y; xs[q*4+2]=v.z; xs[q*4+3]=v.w;
        }

#pragma unroll
        for (int r = 0; r < 2; ++r) {
#pragma unroll
            for (int nc = 0; nc < 2; ++nc) {
                const int base = c * CHUNK_K + nc * 12;   // leaf offset in span

                float a1[12], a2[12], m1[12], m2[12], gg[12], w0v[12];
                SLD12(a1,  &s_syn[0][r][base]);
                SLD12(a2,  &s_syn[1][r][base]);
                SLD12(m1,  &s_syn[2][r][base]);
                SLD12(m2,  &s_syn[3][r][base]);
                SLD12(gg,  &s_syn[4][r][base]);
                SLD12(w0v, &s_syn[5][r][base]);

                float s[12];
#pragma unroll
                for (int t = 0; t < 12; ++t)
                    s[t] = synapse(xs[nc*12 + t], a1[t], a2[t], m1[t], m2[t], gg[t]);

                // level 0 (f=3): 4 nodes
                float n1[4];
#pragma unroll
                for (int i2 = 0; i2 < 4; ++i2) {
                    float acc = s_b0[r][base/3 + i2];
                    acc = fmaf(s[3*i2+0], w0v[3*i2+0], acc);
                    acc = fmaf(s[3*i2+1], w0v[3*i2+1], acc);
                    acc = fmaf(s[3*i2+2], w0v[3*i2+2], acc);
                    n1[i2] = leaky(acc);
                }
                // level 1 (f=2): 2 nodes
                float n2[2];
#pragma unroll
                for (int i2 = 0; i2 < 2; ++i2) {
                    int nl = base/6 + i2;
                    float acc = s_b1[r][nl];
                    acc = fmaf(n1[2*i2+0], s_w1[r][2*nl+0], acc);
                    acc = fmaf(n1[2*i2+1], s_w1[r][2*nl+1], acc);
                    n2[i2] = leaky(acc);
                }
                // level 2 (f=2): 1 node -> K=256 value
                int nl2 = base / 12;
                float acc = s_b2[r][nl2];
                acc = fmaf(n2[0], s_w2[r][2*nl2+0], acc);
                acc = fmaf(n2[1], s_w2[r][2*nl2+1], acc);
                float v = leaky(acc);

                int ng = blockIdx.y * 16 + c * 2 + nc;    // global node 0..255
                g_n256[((size_t)(r * 256 + ng) << 13) + row] = v;   // coalesced STG
            }
        }
    }
}

// upper tree: K=256 -> 1 for one (row, r)
__global__ void __launch_bounds__(128) k2_upper(K2Params P)
{
    // w3..w10 flattened: level l has N_l = 128>>l nodes, 2 floats each
    __shared__ float s_w[2][510];
    __shared__ float s_b[2][255];

    const int tid = threadIdx.x;
    // stage params (one-time, broadcast-consumed)
    for (int i = tid; i < 2 * 510; i += 128) {
        int r = i / 510, j = i % 510;
        int l = 0, off = 0;
        while (j >= off + (256 >> l)) { off += 256 >> l; ++l; }   // level of j
        s_w[r][j] = P.w[l][r * (256 >> l) + (j - off)];
    }
    for (int i = tid; i < 2 * 255; i += 128) {
        int r = i / 255, j = i % 255;
        int l = 0, off = 0;
        while (j >= off + (128 >> l)) { off += 128 >> l; ++l; }
        s_b[r][j] = P.b[l][r * (128 >> l) + (j - off)];
    }
    __syncthreads();

    const int idx = blockIdx.x * 128 + tid;   // 0..16383
    const int r   = idx >> 13;
    const int row = idx & (NROWS - 1);
    const float* src = g_n256 + ((size_t)r << 21) + row;   // r*256*8192

#define WOFF(l) (512 - (512 >> (l)))
#define BOFF(l) (256 - (256 >> (l)))
#define MERGE(l, a, bb, nidx) \
    leaky(fmaf((bb), s_w[r][WOFF(l) + 2*(nidx) + 1], \
          fmaf((a),  s_w[r][WOFF(l) + 2*(nidx)],     \
               s_b[r][BOFF(l) + (nidx)])))

    float c3, c4, c5, c6, c7, res = 0.f;
#pragma unroll
    for (int g = 0; g < 32; ++g) {
        // load 8 node values (independent -> MLP 8), merge levels 0..2
        float v[8];
#pragma unroll
        for (int i = 0; i < 8; ++i)
            v[i] = src[(size_t)(g * 8 + i) << 13];
        float p0 = MERGE(0, v[0], v[1], g*4 + 0);
        float p1 = MERGE(0, v[2], v[3], g*4 + 1);
        float p2 = MERGE(0, v[4], v[5], g*4 + 2);
        float p3 = MERGE(0, v[6], v[7], g*4 + 3);
        float q0 = MERGE(1, p0, p1, g*2 + 0);
        float q1 = MERGE(1, p2, p3, g*2 + 1);
        float t  = MERGE(2, q0, q1, g);
        // static carry-chain for levels 3..7 (g is compile-time constant)
        if (g & 1) {
            t = MERGE(3, c3, t, g >> 1);
            if (g & 2) {
                t = MERGE(4, c4, t, g >> 2);
                if (g & 4) {
                    t = MERGE(5, c5, t, g >> 3);
                    if (g & 8) {
                        t = MERGE(6, c6, t, g >> 4);
                        if (g & 16) res = MERGE(7, c7, t, 0);
                        else        c7 = t;
                    } else c6 = t;
                } else c5 = t;
            } else c4 = t;
        } else c3 = t;
    }
    g_y[idx] = res;
#undef MERGE
#undef WOFF
#undef BOFF
}

__global__ void k3_root(const float* __restrict__ root_w,
                        const float* __restrict__ root_b,
                        float* __restrict__ out)
{
    int row = blockIdx.x * 256 + threadIdx.x;
    if (row < NROWS) {
        float rw0 = root_w[0], rw1 = root_w[1], rb = root_b[0];
        out[row] = fmaf(g_y[NROWS + row], rw1, fmaf(g_y[row], rw0, rb));
    }
}

extern "C" void kernel_launch(void* const* d_in, const int* in_sizes, int n_in,
                              void* d_out, int out_size)
{
    const float* w[11];
    const float* b[11];
    // interleaved (dict order) vs grouped (signature order), via in_sizes[8]
    bool interleaved = (in_sizes[8] == 2048);
    for (int i = 0; i < 11; ++i) {
        if (interleaved) {
            w[i] = (const float*)d_in[6 + 2 * i];
            b[i] = (const float*)d_in[7 + 2 * i];
        } else {
            w[i] = (const float*)d_in[6 + i];
            b[i] = (const float*)d_in[17 + i];
        }
    }

    K1Params P1;
    P1.x   = (const float*)d_in[0];
    P1.ap1 = (const float*)d_in[1];
    P1.ap2 = (const float*)d_in[2];
    P1.am1 = (const float*)d_in[3];
    P1.am2 = (const float*)d_in[4];
    P1.g0  = (const float*)d_in[5];
    P1.w0 = w[0]; P1.b0 = b[0];
    P1.w1 = w[1]; P1.b1 = b[1];
    P1.w2 = w[2]; P1.b2 = b[2];

    K2Params P2;
    for (int l = 0; l < 8; ++l) { P2.w[l] = w[3 + l]; P2.b[l] = b[3 + l]; }

    k1_synapse_lower<<<dim3(32, 16), 256>>>(P1);
    k2_upper<<<128, 128>>>(P2);
    k3_root<<<32, 256>>>((const float*)d_in[28], (const float*)d_in[29],
                         (float*)d_out);
}

// round 3
// speedup vs baseline: 4.1131x; 1.1541x over previous
#include <cuda_runtime.h>

// ---------------------------------------------------------------------------
// B=8192 rows, R=2, K0=3072 leaves; tree 3072 ->(f=3) 1024 ->(f=2)... -> 1
// k0_prep: prescale synapse params (x log2e, g0 x 5) into packed per-group SoA.
// k1: block = 256 rows x 8 groups (96 leaves). x staged via smem (coalesced),
//     params broadcast-LDS from packed scratch. Synapse (clamp-free, algebra-
//     reduced) + tree levels 0..2 -> K=256 node scratch [r][node][row].
// k2: thread = row; collapses K=256 -> 1 for both r + root combine -> out.
// ---------------------------------------------------------------------------

#define NROWS   8192
#define KSPAN   96
#define NGRP    8          // 12-leaf groups per block span
#define XSTRIDE 28         // padded smem stride: conflict-free LDS.128

__device__ float g_n256[2 * 256 * NROWS];        // [r][node][row]
__device__ float g_pk[2 * 256 * 6 * 12];         // [r][group][{a1,a2,m1,m2,gz5,w0}][12]

struct K1Params {
    const float *x;
    const float *b0, *w1, *b1, *w2, *b2;
};
struct K2Params {
    const float* w[8];   // w3..w10
    const float* b[8];   // b3..b10
    const float *root_w, *root_b;
    float* out;
};

__device__ __forceinline__ float ex2f(float x) {
    float y; asm("ex2.approx.ftz.f32 %0, %1;" : "=f"(y) : "f"(x)); return y;
}
__device__ __forceinline__ float rcpf(float x) {
    float y; asm("rcp.approx.ftz.f32 %0, %1;" : "=f"(y) : "f"(x)); return y;
}
__device__ __forceinline__ float leaky(float y) {
    return fmaxf(y, 0.01f * y);
}

#define SLD12(dst, ptr) do { \
    float4 _a = *(const float4*)((ptr));     \
    float4 _b = *(const float4*)((ptr) + 4); \
    float4 _c = *(const float4*)((ptr) + 8); \
    dst[0]=_a.x; dst[1]=_a.y; dst[2]=_a.z; dst[3]=_a.w; \
    dst[4]=_b.x; dst[5]=_b.y; dst[6]=_b.z; dst[7]=_b.w; \
    dst[8]=_c.x; dst[9]=_c.y; dst[10]=_c.z; dst[11]=_c.w; } while (0)

// ---- prep: pack + prescale synapse params -------------------------------
__global__ void k0_prep(const float* __restrict__ ap1, const float* __restrict__ ap2,
                        const float* __restrict__ am1, const float* __restrict__ am2,
                        const float* __restrict__ g0,  const float* __restrict__ w0)
{
    const float L2E = 1.4426950408889634f;
    int idx = blockIdx.x * 512 + threadIdx.x;       // 0..6143 = r*3072+k
    if (idx >= 6144) return;
    int r = idx >> 11;   // /3072? careful: 3072 not pow2
    r = idx / 3072;
    int k = idx - r * 3072;
    int g = k / 12, t = k - g * 12;
    float* base = g_pk + ((size_t)(r * 256 + g) * 6) * 12 + t;
    base[0]  = ap1[idx] * L2E;
    base[12] = ap2[idx] * L2E;
    base[24] = am1[idx] * L2E;
    base[36] = am2[idx] * L2E;
    base[48] = g0[idx] * 5.0f;
    base[60] = w0[idx];          // w0 (R,1024,3) flattens to leaf order
}

// ---- k1: synapse + tree levels 0..2 --------------------------------------
__global__ void __launch_bounds__(256) k1_synapse_lower(K1Params P)
{
    __shared__ float s_pk[2][NGRP][6][12];
    __shared__ float s_b0[2][32];
    __shared__ float s_w1[2][32];
    __shared__ float s_b1[2][16];
    __shared__ float s_w2[2][16];
    __shared__ float s_b2[2][8];
    __shared__ float s_x[256 * XSTRIDE];

    const int tid = threadIdx.x;
    const int r0  = blockIdx.x * 256;
    const int k0  = blockIdx.y * KSPAN;
    const int g0b = blockIdx.y * NGRP;
    const int row = r0 + tid;

    // ---- stage packed synapse params (coalesced, 1152 floats) ----
    {
        const float* src = g_pk + (size_t)g0b * 72;          // r=0 slice
        float* dst = &s_pk[0][0][0][0];
        for (int i = tid; i < NGRP * 72; i += 256) dst[i] = src[i];
        src = g_pk + (size_t)(256 + g0b) * 72;               // r=1 slice
        dst = &s_pk[1][0][0][0];
        for (int i = tid; i < NGRP * 72; i += 256) dst[i] = src[i];

        if (tid < 64)  { int r=tid>>5, j=tid&31; s_b0[r][j] = P.b0[r*1024 + k0/3 + j]; }
        else if (tid < 128) { int u=tid-64; int r=u>>5, j=u&31; s_w1[r][j] = P.w1[r*1024 + k0/3 + j]; }
        else if (tid < 160) { int u=tid-128; int r=u>>4, j=u&15; s_b1[r][j] = P.b1[r*512 + k0/6 + j]; }
        else if (tid < 192) { int u=tid-160; int r=u>>4, j=u&15; s_w2[r][j] = P.w2[r*512 + k0/6 + j]; }
        else if (tid < 208) { int u=tid-192; int r=u>>3, j=u&7;  s_b2[r][j] = P.b2[r*256 + k0/12 + j]; }
    }

    const float* xbase = P.x + (size_t)r0 * 3072 + k0;

#pragma unroll
    for (int c = 0; c < 4; ++c) {                  // 4 chunks of 24 leaves
        __syncthreads();
        // coalesced cooperative load: 256 rows x 24 floats
#pragma unroll
        for (int it = 0; it < 6; ++it) {
            int i  = it * 256 + tid;
            int rw = i / 6, cc = i - rw * 6;
            float4 v = __ldcs((const float4*)(xbase + (size_t)rw * 3072 + c * 24 + cc * 4));
            *(float4*)&s_x[rw * XSTRIDE + cc * 4] = v;
        }
        __syncthreads();

        float xs[24];
#pragma unroll
        for (int q = 0; q < 6; ++q) {
            float4 v = *(const float4*)&s_x[tid * XSTRIDE + q * 4];
            xs[q*4+0]=v.x; xs[q*4+1]=v.y; xs[q*4+2]=v.z; xs[q*4+3]=v.w;
        }

#pragma unroll
        for (int r = 0; r < 2; ++r) {
#pragma unroll
            for (int nc = 0; nc < 2; ++nc) {
                const int g = c * 2 + nc;               // group in span (compile-time)
                float a1[12], a2[12], m1[12], m2[12], gz[12], w0v[12];
                SLD12(a1,  &s_pk[r][g][0][0]);
                SLD12(a2,  &s_pk[r][g][1][0]);
                SLD12(m1,  &s_pk[r][g][2][0]);
                SLD12(m2,  &s_pk[r][g][3][0]);
                SLD12(gz,  &s_pk[r][g][4][0]);
                SLD12(w0v, &s_pk[r][g][5][0]);

                float s[12];
#pragma unroll
                for (int t = 0; t < 12; ++t) {
                    float xv = xs[nc * 12 + t];
                    float gp = ex2f(fmaf(a1[t], xv, a2[t]));
                    float gm = ex2f(fmaf(m1[t], xv, m2[t]));
                    float den = fmaf(0.2f, gz[t], gp + gm);
                    float num = fmaf(gp, 120.f, gz[t]);
                    s[t] = fmaf(num, rcpf(den), -70.f);
                }

                // level 0 (f=3): 4 nodes
                float n1[4];
#pragma unroll
                for (int i2 = 0; i2 < 4; ++i2) {
                    float acc = s_b0[r][g * 4 + i2];
                    acc = fmaf(s[3*i2+0], w0v[3*i2+0], acc);
                    acc = fmaf(s[3*i2+1], w0v[3*i2+1], acc);
                    acc = fmaf(s[3*i2+2], w0v[3*i2+2], acc);
                    n1[i2] = leaky(acc);
                }
                // level 1 (f=2): 2 nodes
                float n2[2];
#pragma unroll
                for (int i2 = 0; i2 < 2; ++i2) {
                    int nl = g * 2 + i2;
                    float acc = s_b1[r][nl];
                    acc = fmaf(n1[2*i2+0], s_w1[r][2*nl+0], acc);
                    acc = fmaf(n1[2*i2+1], s_w1[r][2*nl+1], acc);
                    n2[i2] = leaky(acc);
                }
                // level 2 (f=2): K=256 node
                float acc = s_b2[r][g];
                acc = fmaf(n2[0], s_w2[r][2*g+0], acc);
                acc = fmaf(n2[1], s_w2[r][2*g+1], acc);
                float v = leaky(acc);

                g_n256[((size_t)(r * 256 + g0b + g) << 13) + row] = v;
            }
        }
    }
}

// ---- k2: upper tree K=256 -> 1, both r, + root combine --------------------
__global__ void __launch_bounds__(128) k2_upper(K2Params P)
{
    __shared__ float s_w[2][510];
    __shared__ float s_b[2][255];

    const int tid = threadIdx.x;
    for (int i = tid; i < 2 * 510; i += 128) {
        int r = i / 510, j = i - r * 510;
        int l = 0, off = 0;
        while (j >= off + (256 >> l)) { off += 256 >> l; ++l; }
        s_w[r][j] = P.w[l][r * (256 >> l) + (j - off)];
    }
    for (int i = tid; i < 2 * 255; i += 128) {
        int r = i / 255, j = i - r * 255;
        int l = 0, off = 0;
        while (j >= off + (128 >> l)) { off += 128 >> l; ++l; }
        s_b[r][j] = P.b[l][r * (128 >> l) + (j - off)];
    }
    __syncthreads();

    const int row = blockIdx.x * 128 + tid;

#define WOFF(l) (512 - (512 >> (l)))
#define BOFF(l) (256 - (256 >> (l)))
#define MERGE(l, a, bb, nidx) \
    leaky(fmaf((bb), s_w[r][WOFF(l) + 2*(nidx) + 1], \
          fmaf((a),  s_w[r][WOFF(l) + 2*(nidx)],     \
               s_b[r][BOFF(l) + (nidx)])))

    float yfin[2];
#pragma unroll
    for (int r = 0; r < 2; ++r) {
        const float* src = g_n256 + ((size_t)r << 21) + row;
        float c3, c4, c5, c6, c7, res = 0.f;
#pragma unroll
        for (int g = 0; g < 32; ++g) {
            float v[8];
#pragma unroll
            for (int i = 0; i < 8; ++i)
                v[i] = src[(size_t)(g * 8 + i) << 13];
            float p0 = MERGE(0, v[0], v[1], g*4 + 0);
            float p1 = MERGE(0, v[2], v[3], g*4 + 1);
            float p2 = MERGE(0, v[4], v[5], g*4 + 2);
            float p3 = MERGE(0, v[6], v[7], g*4 + 3);
            float q0 = MERGE(1, p0, p1, g*2 + 0);
            float q1 = MERGE(1, p2, p3, g*2 + 1);
            float t  = MERGE(2, q0, q1, g);
            if (g & 1) {
                t = MERGE(3, c3, t, g >> 1);
                if (g & 2) {
                    t = MERGE(4, c4, t, g >> 2);
                    if (g & 4) {
                        t = MERGE(5, c5, t, g >> 3);
                        if (g & 8) {
                            t = MERGE(6, c6, t, g >> 4);
                            if (g & 16) res = MERGE(7, c7, t, 0);
                            else        c7 = t;
                        } else c6 = t;
                    } else c5 = t;
                } else c4 = t;
            } else c3 = t;
        }
        yfin[r] = res;
    }
#undef MERGE
#undef WOFF
#undef BOFF

    float rw0 = P.root_w[0], rw1 = P.root_w[1], rb = P.root_b[0];
    P.out[row] = fmaf(yfin[1], rw1, fmaf(yfin[0], rw0, rb));
}

extern "C" void kernel_launch(void* const* d_in, const int* in_sizes, int n_in,
                              void* d_out, int out_size)
{
    const float* w[11];
    const float* b[11];
    bool interleaved = (in_sizes[8] == 2048);
    for (int i = 0; i < 11; ++i) {
        if (interleaved) {
            w[i] = (const float*)d_in[6 + 2 * i];
            b[i] = (const float*)d_in[7 + 2 * i];
        } else {
            w[i] = (const float*)d_in[6 + i];
            b[i] = (const float*)d_in[17 + i];
        }
    }

    k0_prep<<<12, 512>>>((const float*)d_in[1], (const float*)d_in[2],
                         (const float*)d_in[3], (const float*)d_in[4],
                         (const float*)d_in[5], w[0]);

    K1Params P1;
    P1.x  = (const float*)d_in[0];
    P1.b0 = b[0];
    P1.w1 = w[1]; P1.b1 = b[1];
    P1.w2 = w[2]; P1.b2 = b[2];
    k1_synapse_lower<<<dim3(32, 32), 256>>>(P1);

    K2Params P2;
    for (int l = 0; l < 8; ++l) { P2.w[l] = w[3 + l]; P2.b[l] = b[3 + l]; }
    P2.root_w = (const float*)d_in[28];
    P2.root_b = (const float*)d_in[29];
    P2.out    = (float*)d_out;
    k2_upper<<<64, 128>>>(P2);
}

// round 4
// speedup vs baseline: 5.7156x; 1.3896x over previous
#include <cuda_runtime.h>

// ---------------------------------------------------------------------------
// B=8192 rows, R=2, K0=3072; tree 3072 ->(f=3) 1024 ->(f=2)... -> 1
// k1: block = 256 rows x 192-leaf span (16 groups of 12). Prescales params
//     while staging to smem. Synapse + tree levels 0..5 (register carry
//     chain) -> K=32 node scratch [r][node][row] (2MB).
// k2: thread = (row, r): K=32 -> 1 (levels 6..10), shuffle root combine.
// ---------------------------------------------------------------------------

#define NROWS   8192
#define SPAN    192
#define XSTRIDE 28

__device__ float g_n32[2 * 32 * NROWS];   // [r][node][row]

struct K1Params {
    const float *x, *ap1, *ap2, *am1, *am2, *g0;
    const float *w0, *b0, *w1, *b1, *w2, *b2, *w3, *b3, *w4, *b4, *w5, *b5;
};
struct K2Params {
    const float* w[5];   // w6..w10
    const float* b[5];   // b6..b10
    const float *root_w, *root_b;
    float* out;
};

__device__ __forceinline__ float ex2f(float x) {
    float y; asm("ex2.approx.ftz.f32 %0, %1;" : "=f"(y) : "f"(x)); return y;
}
__device__ __forceinline__ float rcpf(float x) {
    float y; asm("rcp.approx.ftz.f32 %0, %1;" : "=f"(y) : "f"(x)); return y;
}
__device__ __forceinline__ float leaky(float y) {
    return fmaxf(y, 0.01f * y);
}

__global__ void __launch_bounds__(256, 4) k1_lower(K1Params P)
{
    __shared__ float4 s_p4[2][SPAN];          // a1*L2E, a2*L2E, m1*L2E, m2*L2E
    __shared__ float2 s_gw[2][SPAN];          // g0*5, w0
    __shared__ float  s_b0[2][64], s_w1[2][64], s_b1[2][32], s_w2[2][32],
                      s_b2[2][16], s_w3[2][16], s_b3[2][8],  s_w4[2][8],
                      s_b4[2][4],  s_w5[2][4],  s_b5[2][2];
    __shared__ float  s_x[256 * XSTRIDE];

    const int tid  = threadIdx.x;
    const int r0   = blockIdx.x * 256;
    const int span = blockIdx.y;
    const int k0   = span * SPAN;
    const int row  = r0 + tid;
    const float L2E = 1.4426950408889634f;

    // ---- stage + prescale synapse params (coalesced per array) ----
    for (int i = tid; i < 2 * SPAN; i += 256) {
        int r = i / SPAN, j = i - r * SPAN;
        int idx = r * 3072 + k0 + j;
        s_p4[r][j] = make_float4(P.ap1[idx] * L2E, P.ap2[idx] * L2E,
                                 P.am1[idx] * L2E, P.am2[idx] * L2E);
        s_gw[r][j] = make_float2(P.g0[idx] * 5.0f, P.w0[idx]);
    }
    // ---- stage level params ----
    if (tid < 128)      { int r=tid>>6, j=tid&63;            s_b0[r][j] = P.b0[r*1024 + span*64 + j]; }
    else                { int u=tid-128, r=u>>6, j=u&63;     s_w1[r][j] = P.w1[r*1024 + span*64 + j]; }
    if (tid < 64)       { int r=tid>>5, j=tid&31;            s_b1[r][j] = P.b1[r*512 + span*32 + j]; }
    else if (tid < 128) { int u=tid-64,  r=u>>5, j=u&31;     s_w2[r][j] = P.w2[r*512 + span*32 + j]; }
    else if (tid < 160) { int u=tid-128, r=u>>4, j=u&15;     s_b2[r][j] = P.b2[r*256 + span*16 + j]; }
    else if (tid < 192) { int u=tid-160, r=u>>4, j=u&15;     s_w3[r][j] = P.w3[r*256 + span*16 + j]; }
    else if (tid < 208) { int u=tid-192, r=u>>3, j=u&7;      s_b3[r][j] = P.b3[r*128 + span*8 + j]; }
    else if (tid < 224) { int u=tid-208, r=u>>3, j=u&7;      s_w4[r][j] = P.w4[r*128 + span*8 + j]; }
    else if (tid < 232) { int u=tid-224, r=u>>2, j=u&3;      s_b4[r][j] = P.b4[r*64 + span*4 + j]; }
    else if (tid < 240) { int u=tid-232, r=u>>2, j=u&3;      s_w5[r][j] = P.w5[r*64 + span*4 + j]; }
    else if (tid < 244) { int u=tid-240, r=u>>1, j=u&1;      s_b5[r][j] = P.b5[r*32 + span*2 + j]; }

    const float* xbase = P.x + (size_t)r0 * 3072 + k0;
    float c3[2], c4[2], c5[2];

#pragma unroll
    for (int c = 0; c < 8; ++c) {              // 8 chunks of 24 leaves
        __syncthreads();
        // cooperative coalesced x load: 256 rows x 24 floats
#pragma unroll
        for (int it = 0; it < 6; ++it) {
            int i  = it * 256 + tid;
            int rw = i / 6, cc = i - rw * 6;
            float4 v = __ldcs((const float4*)(xbase + (size_t)rw * 3072 + c * 24 + cc * 4));
            *(float4*)&s_x[rw * XSTRIDE + cc * 4] = v;
        }
        __syncthreads();

        float xs[24];
#pragma unroll
        for (int q = 0; q < 6; ++q) {
            float4 v = *(const float4*)&s_x[tid * XSTRIDE + q * 4];
            xs[q*4+0]=v.x; xs[q*4+1]=v.y; xs[q*4+2]=v.z; xs[q*4+3]=v.w;
        }

#pragma unroll
        for (int nc = 0; nc < 2; ++nc) {
            const int g = c * 2 + nc;          // group 0..15 (compile-time)
#pragma unroll
            for (int r = 0; r < 2; ++r) {
                float n1[4];
#pragma unroll
                for (int i2 = 0; i2 < 4; ++i2) {
                    float acc = s_b0[r][g * 4 + i2];
#pragma unroll
                    for (int t = 0; t < 3; ++t) {
                        const int leaf = g * 12 + 3 * i2 + t;
                        float4 p  = s_p4[r][leaf];
                        float2 gw = s_gw[r][leaf];
                        float xv  = xs[nc * 12 + 3 * i2 + t];
                        float gp  = ex2f(fmaf(p.x, xv, p.y));
                        float gm  = ex2f(fmaf(p.z, xv, p.w));
                        float den = fmaf(0.2f, gw.x, gp + gm);
                        float num = fmaf(gp, 120.f, gw.x);
                        acc = fmaf(fmaf(num, rcpf(den), -70.f), gw.y, acc);
                    }
                    n1[i2] = leaky(acc);
                }
                float n2a = leaky(fmaf(n1[1], s_w1[r][4*g+1], fmaf(n1[0], s_w1[r][4*g+0], s_b1[r][2*g+0])));
                float n2b = leaky(fmaf(n1[3], s_w1[r][4*g+3], fmaf(n1[2], s_w1[r][4*g+2], s_b1[r][2*g+1])));
                float v   = leaky(fmaf(n2b,  s_w2[r][2*g+1], fmaf(n2a,  s_w2[r][2*g+0], s_b2[r][g])));

                // carry-chain merge, levels 3..5 (g compile-time)
                if ((g & 1) == 0) { c3[r] = v; }
                else {
                    const int p3 = g >> 1;
                    v = leaky(fmaf(v, s_w3[r][2*p3+1], fmaf(c3[r], s_w3[r][2*p3], s_b3[r][p3])));
                    if ((g & 3) == 1) { c4[r] = v; }
                    else {
                        const int p4i = g >> 2;
                        v = leaky(fmaf(v, s_w4[r][2*p4i+1], fmaf(c4[r], s_w4[r][2*p4i], s_b4[r][p4i])));
                        if ((g & 7) == 3) { c5[r] = v; }
                        else {
                            const int p5 = g >> 3;
                            v = leaky(fmaf(v, s_w5[r][2*p5+1], fmaf(c5[r], s_w5[r][2*p5], s_b5[r][p5])));
                            g_n32[((size_t)(r * 32 + span * 2 + p5) << 13) + row] = v;
                        }
                    }
                }
            }
        }
    }
}

// ---- k2: K=32 -> 1 per (row, r), shuffle root combine ---------------------
__global__ void __launch_bounds__(128) k2_upper(K2Params P)
{
    __shared__ float s_w[2][62];   // w6(32) w7(16) w8(8) w9(4) w10(2)
    __shared__ float s_b[2][31];   // b6(16) b7(8) b8(4) b9(2) b10(1)
    __shared__ float s_root[3];

    const int tid = threadIdx.x;
    for (int i = tid; i < 124; i += 128) {
        int r = i / 62, j = i - r * 62;
        int l = 0, off = 0;
        while (j >= off + (32 >> l)) { off += 32 >> l; ++l; }
        s_w[r][j] = P.w[l][r * (32 >> l) + (j - off)];
    }
    if (tid < 62) {
        int r = tid / 31, j = tid - r * 31;
        int l = 0, off = 0;
        while (j >= off + (16 >> l)) { off += 16 >> l; ++l; }
        s_b[r][j] = P.b[l][r * (16 >> l) + (j - off)];
    }
    if (tid == 0) { s_root[0] = P.root_w[0]; s_root[1] = P.root_w[1]; s_root[2] = P.root_b[0]; }
    __syncthreads();

    const int idx = blockIdx.x * 128 + tid;   // 0..16383
    const int row = idx >> 1;
    const int r   = idx & 1;
    const float* src = g_n32 + ((size_t)r << 18) + row;

    float v[32];
#pragma unroll
    for (int i = 0; i < 32; ++i) v[i] = src[(size_t)i << 13];

#pragma unroll
    for (int i = 0; i < 16; ++i)
        v[i] = leaky(fmaf(v[2*i+1], s_w[r][2*i+1],     fmaf(v[2*i], s_w[r][2*i],     s_b[r][i])));
#pragma unroll
    for (int i = 0; i < 8; ++i)
        v[i] = leaky(fmaf(v[2*i+1], s_w[r][32+2*i+1],  fmaf(v[2*i], s_w[r][32+2*i],  s_b[r][16+i])));
#pragma unroll
    for (int i = 0; i < 4; ++i)
        v[i] = leaky(fmaf(v[2*i+1], s_w[r][48+2*i+1],  fmaf(v[2*i], s_w[r][48+2*i],  s_b[r][24+i])));
#pragma unroll
    for (int i = 0; i < 2; ++i)
        v[i] = leaky(fmaf(v[2*i+1], s_w[r][56+2*i+1],  fmaf(v[2*i], s_w[r][56+2*i],  s_b[r][28+i])));
    float y = leaky(fmaf(v[1], s_w[r][61], fmaf(v[0], s_w[r][60], s_b[r][30])));

    float yo = __shfl_xor_sync(0xFFFFFFFFu, y, 1);
    if (r == 0)
        P.out[row] = fmaf(yo, s_root[1], fmaf(y, s_root[0], s_root[2]));
}

extern "C" void kernel_launch(void* const* d_in, const int* in_sizes, int n_in,
                              void* d_out, int out_size)
{
    const float* w[11];
    const float* b[11];
    bool interleaved = (in_sizes[8] == 2048);
    for (int i = 0; i < 11; ++i) {
        if (interleaved) {
            w[i] = (const float*)d_in[6 + 2 * i];
            b[i] = (const float*)d_in[7 + 2 * i];
        } else {
            w[i] = (const float*)d_in[6 + i];
            b[i] = (const float*)d_in[17 + i];
        }
    }

    K1Params P1;
    P1.x   = (const float*)d_in[0];
    P1.ap1 = (const float*)d_in[1];
    P1.ap2 = (const float*)d_in[2];
    P1.am1 = (const float*)d_in[3];
    P1.am2 = (const float*)d_in[4];
    P1.g0  = (const float*)d_in[5];
    P1.w0 = w[0]; P1.b0 = b[0];
    P1.w1 = w[1]; P1.b1 = b[1];
    P1.w2 = w[2]; P1.b2 = b[2];
    P1.w3 = w[3]; P1.b3 = b[3];
    P1.w4 = w[4]; P1.b4 = b[4];
    P1.w5 = w[5]; P1.b5 = b[5];
    k1_lower<<<dim3(32, 16), 256>>>(P1);

    K2Params P2;
    for (int l = 0; l < 5; ++l) { P2.w[l] = w[6 + l]; P2.b[l] = b[6 + l]; }
    P2.root_w = (const float*)d_in[28];
    P2.root_b = (const float*)d_in[29];
    P2.out    = (float*)d_out;
    k2_upper<<<128, 128>>>(P2);
}